// round 11
// baseline (speedup 1.0000x reference)
#include <cuda_runtime.h>
#include <cuda_bf16.h>

// ChamferDistance: B=8, N=4096, D=3.
// Round 11: two structural fixes over round 10.
// (1) Per-lane candidate scanning: each lane walks its OWN z-window with its
//     own pointer, so every LDS.128 wavefront serves 32 distinct candidates
//     instead of broadcasting one (32x useful smem bandwidth).
// (2) Probe -> bound -> single scan: each lane probes 32 targets around its
//     z-rank (true NN upper bound ub), then scans buckets
//     [bucket(z-r), bucket(z+r)], r=sqrt(ub). z_bucket is monotone, so the
//     window provably contains the NN: exact, no ring loop, no fallback.
// Build fused into ONE kernel (per-cloud: smem histogram -> scan -> scatter).
// 2 launches total. Deterministic fixed-order reductions.

#define CD_B 8
#define CD_N 4096
#define CD_NCLOUD 16
#define CD_NB 512
#define CD_ZMIN (-6.0f)
#define CD_ZW (12.0f / CD_NB)
#define CD_INVZW (CD_NB / 12.0f)
#define CD_QTPB 256
#define CD_QBLKX (CD_N / CD_QTPB)        // 16
#define CD_NPART (CD_QBLKX * CD_B * 2)   // 256
#define CD_BTPB 512
#define CD_PPT (CD_N / CD_BTPB)          // 8 points per build thread

// dynamic smem: cloud (64KB) + offsets (513 ints, pad to 2064B) + red (1KB)
#define CD_SMEM_PTS_BYTES (CD_N * 16)
#define CD_SMEM_TOTAL (CD_SMEM_PTS_BYTES + 2064 + CD_QTPB * 4)

__device__ int    g_start[CD_NCLOUD][CD_NB];
__device__ float4 g_sorted[CD_NCLOUD][CD_N];
__device__ float  g_part[CD_NPART];
__device__ unsigned int g_fcnt;

__device__ __forceinline__ int z_bucket(float z) {
    int bk = (int)((z - CD_ZMIN) * CD_INVZW);
    return max(0, min(CD_NB - 1, bk));
}

// One block per cloud: histogram -> scan -> scatter, all in smem.
__global__ __launch_bounds__(CD_BTPB)
void cd_build_kernel(const float* __restrict__ p1,
                     const float* __restrict__ p2) {
    __shared__ int s_cnt[CD_NB];
    __shared__ int s_scan[CD_NB];
    __shared__ int s_cur[CD_NB];

    const int c   = blockIdx.x;
    const int tid = threadIdx.x;
    const float* base = (c < CD_B) ? p1 + (size_t)c * CD_N * 3
                                   : p2 + (size_t)(c - CD_B) * CD_N * 3;

    if (tid < CD_NB) s_cnt[tid] = 0;
    __syncthreads();

    // Histogram (coalesced reads; smem atomics).
    float zbuf[CD_PPT];
    #pragma unroll
    for (int k = 0; k < CD_PPT; k++) {
        const int i = k * CD_BTPB + tid;
        zbuf[k] = base[i * 3 + 2];
        atomicAdd(&s_cnt[z_bucket(zbuf[k])], 1);
    }
    __syncthreads();

    // Exclusive scan over 512 buckets (Hillis-Steele on first 512 threads).
    if (tid < CD_NB) s_scan[tid] = s_cnt[tid];
    __syncthreads();
    #pragma unroll
    for (int off = 1; off < CD_NB; off <<= 1) {
        int add = 0;
        if (tid < CD_NB && tid >= off) add = s_scan[tid - off];
        __syncthreads();
        if (tid < CD_NB) s_scan[tid] += add;
        __syncthreads();
    }
    if (tid < CD_NB) {
        int excl = s_scan[tid] - s_cnt[tid];
        s_cur[tid] = excl;
        g_start[c][tid] = excl;
    }
    __syncthreads();

    // Scatter (re-read xy; L1-hot).
    #pragma unroll
    for (int k = 0; k < CD_PPT; k++) {
        const int i = k * CD_BTPB + tid;
        float x = base[i * 3], y = base[i * 3 + 1], z = zbuf[k];
        int pos = atomicAdd(&s_cur[z_bucket(z)], 1);
        g_sorted[c][pos] = make_float4(x, y, z, x * x + y * y + z * z);
    }
}

__global__ __launch_bounds__(CD_QTPB)
void cd_query_kernel(float* __restrict__ out) {
    extern __shared__ char dynsmem[];
    float4* s_pts = reinterpret_cast<float4*>(dynsmem);
    int*    s_off = reinterpret_cast<int*>(dynsmem + CD_SMEM_PTS_BYTES);
    float*  red   = reinterpret_cast<float*>(dynsmem + CD_SMEM_PTS_BYTES + 2064);
    __shared__ int s_flag;

    const int tid = threadIdx.x;
    const int b   = blockIdx.y;
    const int dir = blockIdx.z;
    const int qc  = dir ? (CD_B + b) : b;
    const int tc  = dir ? b : (CD_B + b);
    const int qbase = blockIdx.x * CD_QTPB;

    const float4 q = g_sorted[qc][qbase + tid];
    const float nx0 = -2.0f * q.x;
    const float nx1 = -2.0f * q.y;
    const float nx2 = -2.0f * q.z;
    const int kb = z_bucket(q.z);

    // Stage entire target cloud + bucket offsets (coalesced, high MLP).
    #pragma unroll
    for (int j = tid; j < CD_N; j += CD_QTPB)
        s_pts[j] = g_sorted[tc][j];
    for (int k = tid; k < CD_NB; k += CD_QTPB)
        s_off[k] = g_start[tc][k];
    if (tid == 0) s_off[CD_NB] = CD_N;
    __syncthreads();

    float m0 = 3.402823466e38f, m1 = 3.402823466e38f;

    // Probe: 32 candidates around this lane's z-rank -> NN upper bound.
    {
        int p0 = min(max(s_off[kb] - 16, 0), CD_N - 32);
        #pragma unroll 4
        for (int j = p0; j < p0 + 32; j += 2) {
            float4 t0 = s_pts[j];
            float4 t1 = s_pts[j + 1];
            m0 = fminf(m0, fmaf(nx0, t0.x, fmaf(nx1, t0.y, fmaf(nx2, t0.z, t0.w))));
            m1 = fminf(m1, fmaf(nx0, t1.x, fmaf(nx1, t1.y, fmaf(nx2, t1.z, t1.w))));
        }
    }

    // Window from the bound (monotone z_bucket => provably contains the NN).
    const float ub = fmaxf(fminf(m0, m1) + q.w, 0.0f);
    const float r  = sqrtf(ub) + 1e-5f;
    const int jlo = s_off[z_bucket(q.z - r)];
    const int jhi = s_off[z_bucket(q.z + r) + 1];

    // Per-lane scan: each lane walks its own interval (distinct LDS addrs).
    int j = jlo;
    for (; j + 2 <= jhi; j += 2) {
        float4 t0 = s_pts[j];
        float4 t1 = s_pts[j + 1];
        m0 = fminf(m0, fmaf(nx0, t0.x, fmaf(nx1, t0.y, fmaf(nx2, t0.z, t0.w))));
        m1 = fminf(m1, fmaf(nx0, t1.x, fmaf(nx1, t1.y, fmaf(nx2, t1.z, t1.w))));
    }
    if (j < jhi) {
        float4 t0 = s_pts[j];
        m0 = fminf(m0, fmaf(nx0, t0.x, fmaf(nx1, t0.y, fmaf(nx2, t0.z, t0.w))));
    }

    float val = fmaxf(fminf(m0, m1) + q.w, 0.0f);

    // Deterministic fixed-order block sum.
    red[tid] = val;
    __syncthreads();
    #pragma unroll
    for (int s = CD_QTPB / 2; s > 0; s >>= 1) {
        if (tid < s) red[tid] += red[tid + s];
        __syncthreads();
    }

    if (tid == 0) {
        const int idx = (dir * CD_B + b) * CD_QBLKX + blockIdx.x;
        g_part[idx] = red[0];
        __threadfence();
        unsigned int t = atomicAdd(&g_fcnt, 1u);
        s_flag = (t == CD_NPART - 1);
    }
    __syncthreads();

    if (s_flag) {
        red[tid] = g_part[tid];
        __syncthreads();
        #pragma unroll
        for (int s = CD_QTPB / 2; s > 0; s >>= 1) {
            if (tid < s) red[tid] += red[tid + s];
            __syncthreads();
        }
        if (tid == 0) {
            out[0] = red[0] * (1.0f / ((float)CD_B * (float)CD_N));
            g_fcnt = 0;                              // reset for graph replay
        }
    }
}

extern "C" void kernel_launch(void* const* d_in, const int* in_sizes, int n_in,
                              void* d_out, int out_size) {
    (void)in_sizes; (void)n_in; (void)out_size;
    const float* p1 = (const float*)d_in[0];
    const float* p2 = (const float*)d_in[1];
    float* out = (float*)d_out;

    static bool attr_set = false;
    if (!attr_set) {
        cudaFuncSetAttribute(cd_query_kernel,
                             cudaFuncAttributeMaxDynamicSharedMemorySize,
                             CD_SMEM_TOTAL);
        attr_set = true;
    }

    cd_build_kernel<<<CD_NCLOUD, CD_BTPB>>>(p1, p2);
    dim3 qgrid(CD_QBLKX, CD_B, 2);
    cd_query_kernel<<<qgrid, CD_QTPB, CD_SMEM_TOTAL>>>(out);
}

// round 12
// speedup vs baseline: 3.2613x; 3.2613x over previous
#include <cuda_runtime.h>
#include <cuda_bf16.h>

// ChamferDistance: B=8, N=4096, D=3.
// Round 12: pair-once symmetric brute force. dir0/dir1 evaluate the SAME
// distance set; round-7 computed each twice. Now each (i,j) dist is computed
// once (packed FFMA2 chain + packed ADD2 to fold +xd -> full dist^2):
//   row-min (query i): thread-private accumulators (free)
//   col-min (target j): per-lane q-reduce + 5-level shfl butterfly + lane0
//     encoded atomicMax (key=~bits(v), v>=0: order-free exact float min)
// Halves the FFMA2 stream (the rt-3 RF-bank-limited pipe that floored round 7).
// Final sum kernel decodes/sums all 65536 mins deterministically and resets
// state for graph replay. 2 launches.

#define CD_B 8
#define CD_N 4096
#define CD_TPB 128
#define CD_Q 8
#define CD_QBLK (CD_TPB * CD_Q)          // 1024 queries per block
#define CD_NQB (CD_N / CD_QBLK)          // 4
#define CD_TSPLIT 32
#define CD_TPTS (CD_N / CD_TSPLIT)       // 128 targets per block
#define CD_TPAIRS (CD_TPTS / 2)          // 64 packed pairs
#define CD_SLOTS (2 * CD_B * CD_N)       // 65536 (rows then cols)
#define CD_COL_BASE (CD_B * CD_N)
#define CD_SB 64                          // sum-kernel blocks
#define CD_STPB 256

__device__ unsigned int g_min[CD_SLOTS]; // encoded mins; zero-init; self-reset
__device__ float g_part[CD_SB];
__device__ unsigned int g_fcnt;

typedef unsigned long long u64;

__device__ __forceinline__ u64 pack2(float v) {
    u64 r;
    unsigned int u = __float_as_uint(v);
    asm("mov.b64 %0, {%1, %1};" : "=l"(r) : "r"(u));
    return r;
}

__device__ __forceinline__ u64 fma2(u64 a, u64 b, u64 c) {
    u64 d;
    asm("fma.rn.f32x2 %0, %1, %2, %3;" : "=l"(d) : "l"(a), "l"(b), "l"(c));
    return d;
}

__device__ __forceinline__ u64 add2(u64 a, u64 b) {
    u64 d;
    asm("add.rn.f32x2 %0, %1, %2;" : "=l"(d) : "l"(a), "l"(b));
    return d;
}

__device__ __forceinline__ void unpack2(u64 v, float& lo, float& hi) {
    unsigned int l, h;
    asm("mov.b64 {%0, %1}, %2;" : "=r"(l), "=r"(h) : "l"(v));
    lo = __uint_as_float(l);
    hi = __uint_as_float(h);
}

__global__ __launch_bounds__(CD_TPB, 4)
void cd_pair_kernel(const float* __restrict__ p1,
                    const float* __restrict__ p2) {
    __shared__ float4 sy[CD_TPTS];       // pair-interleaved target tile (2KB)

    const int tid  = threadIdx.x;
    const int ts   = blockIdx.x % CD_TSPLIT;
    const int qblk = blockIdx.x / CD_TSPLIT;
    const int b    = blockIdx.y;

    // Q=8 query points from p1; fold -2 into packed coords; xd packed too.
    u64 xq0[CD_Q], xq1[CD_Q], xq2[CD_Q], xd2[CD_Q];
    float mlo[CD_Q], mhi[CD_Q];
    #pragma unroll
    for (int q = 0; q < CD_Q; q++) {
        const int i = qblk * CD_QBLK + q * CD_TPB + tid;
        const float* xp = p1 + ((size_t)b * CD_N + i) * 3;
        const float x0 = xp[0], x1 = xp[1], x2 = xp[2];
        xd2[q] = pack2(x0 * x0 + x1 * x1 + x2 * x2);
        xq0[q] = pack2(-2.0f * x0);
        xq1[q] = pack2(-2.0f * x1);
        xq2[q] = pack2(-2.0f * x2);
        mlo[q] = 3.402823466e38f;
        mhi[q] = 3.402823466e38f;
    }

    // Target tile from p2 (one pair per thread, first 64 threads).
    if (tid < CD_TPAIRS) {
        const float* yp = p2 + ((size_t)b * CD_N + ts * CD_TPTS + 2 * tid) * 3;
        float e0 = yp[0], e1 = yp[1], e2 = yp[2];
        float o0 = yp[3], o1 = yp[4], o2 = yp[5];
        sy[2 * tid]     = make_float4(e0, o0, e1, o1);
        sy[2 * tid + 1] = make_float4(e2, o2,
                                      e0 * e0 + e1 * e1 + e2 * e2,
                                      o0 * o0 + o1 * o1 + o2 * o2);
    }
    __syncthreads();

    const ulonglong2* __restrict__ syu = reinterpret_cast<const ulonglong2*>(sy);
    const int lane = tid & 31;
    const int colbase = CD_COL_BASE + b * CD_N + ts * CD_TPTS;

    #pragma unroll 2
    for (int p = 0; p < CD_TPAIRS; p++) {
        ulonglong2 A  = syu[2 * p];      // y0 pair, y1 pair
        ulonglong2 Bv = syu[2 * p + 1];  // y2 pair, yd pair
        float ce = 3.402823466e38f, co = 3.402823466e38f;
        #pragma unroll
        for (int q = 0; q < CD_Q; q++) {
            u64 d = fma2(xq2[q], Bv.x, Bv.y);
            d = fma2(xq1[q], A.y, d);
            d = fma2(xq0[q], A.x, d);
            u64 e = add2(d, xd2[q]);     // full dist^2 (lo=target e, hi=target o)
            float elo, ehi;
            unpack2(e, elo, ehi);
            mlo[q] = fminf(mlo[q], elo); // row mins (query-private)
            mhi[q] = fminf(mhi[q], ehi);
            ce = fminf(ce, elo);         // col candidates for this target pair
            co = fminf(co, ehi);
        }
        // Warp butterfly min, then lane0 order-free encoded atomicMax.
        #pragma unroll
        for (int off = 16; off > 0; off >>= 1) {
            ce = fminf(ce, __shfl_xor_sync(0xffffffffu, ce, off));
            co = fminf(co, __shfl_xor_sync(0xffffffffu, co, off));
        }
        if (lane == 0) {
            atomicMax(&g_min[colbase + 2 * p],
                      ~__float_as_uint(fmaxf(ce, 0.0f)));
            atomicMax(&g_min[colbase + 2 * p + 1],
                      ~__float_as_uint(fmaxf(co, 0.0f)));
        }
    }

    // Row mins: one encoded atomicMax per query.
    #pragma unroll
    for (int q = 0; q < CD_Q; q++) {
        const int i = qblk * CD_QBLK + q * CD_TPB + tid;
        float v = fmaxf(fminf(mlo[q], mhi[q]), 0.0f);
        atomicMax(&g_min[b * CD_N + i], ~__float_as_uint(v));
    }
}

__global__ __launch_bounds__(CD_STPB)
void cd_sum_kernel(float* __restrict__ out) {
    __shared__ float red[CD_STPB];
    __shared__ int s_flag;

    const int tid = threadIdx.x;
    const int base = blockIdx.x * (CD_SLOTS / CD_SB) + tid;   // 1024 slots/block

    float acc = 0.0f;
    #pragma unroll
    for (int k = 0; k < CD_SLOTS / CD_SB / CD_STPB; k++) {    // 4 per thread
        const int idx = base + k * CD_STPB;
        unsigned int key = g_min[idx];
        acc += __uint_as_float(~key);
        g_min[idx] = 0u;                                      // reset for replay
    }
    red[tid] = acc;
    __syncthreads();
    #pragma unroll
    for (int s = CD_STPB / 2; s > 0; s >>= 1) {
        if (tid < s) red[tid] += red[tid + s];
        __syncthreads();
    }

    if (tid == 0) {
        g_part[blockIdx.x] = red[0];
        __threadfence();
        unsigned int t = atomicAdd(&g_fcnt, 1u);
        s_flag = (t == CD_SB - 1);
    }
    __syncthreads();

    if (s_flag) {
        float v = (tid < CD_SB) ? g_part[tid] : 0.0f;
        red[tid] = v;
        __syncthreads();
        #pragma unroll
        for (int s = CD_STPB / 2; s > 0; s >>= 1) {
            if (tid < s) red[tid] += red[tid + s];
            __syncthreads();
        }
        if (tid == 0) {
            out[0] = red[0] * (1.0f / ((float)CD_B * (float)CD_N));
            g_fcnt = 0;                                       // reset for replay
        }
    }
}

extern "C" void kernel_launch(void* const* d_in, const int* in_sizes, int n_in,
                              void* d_out, int out_size) {
    (void)in_sizes; (void)n_in; (void)out_size;
    const float* p1 = (const float*)d_in[0];
    const float* p2 = (const float*)d_in[1];
    float* out = (float*)d_out;

    dim3 grid(CD_NQB * CD_TSPLIT, CD_B);   // 128 x 8 = 1024 blocks
    cd_pair_kernel<<<grid, CD_TPB>>>(p1, p2);
    cd_sum_kernel<<<CD_SB, CD_STPB>>>(out);
}

// round 14
// speedup vs baseline: 3.7355x; 1.1454x over previous
#include <cuda_runtime.h>
#include <cuda_bf16.h>

// ChamferDistance: B=8, N=4096, D=3.
// Round 14 (= round 13 resubmitted after infra failure): pair-once structure,
// with the 5-level shfl butterfly (20 SHFL + 20 FMNMX per target pair, ~40%
// of issue slots) replaced by a single redux.sync.max.u32 on the ENCODED key
// (~bits(max(v,0)) — the same order-reversing encode already used for the
// global atomicMax combine). Per pair: 2x(clamp+not+redux) ~ 6 slots vs 40.
// Row mins stay thread-private. Sum kernel vectorized with uint4.

#define CD_B 8
#define CD_N 4096
#define CD_TPB 128
#define CD_Q 8
#define CD_QBLK (CD_TPB * CD_Q)          // 1024 queries per block
#define CD_NQB (CD_N / CD_QBLK)          // 4
#define CD_TSPLIT 32
#define CD_TPTS (CD_N / CD_TSPLIT)       // 128 targets per block
#define CD_TPAIRS (CD_TPTS / 2)          // 64 packed pairs
#define CD_SLOTS (2 * CD_B * CD_N)       // 65536 (rows then cols)
#define CD_COL_BASE (CD_B * CD_N)
#define CD_SB 64
#define CD_STPB 256

__device__ unsigned int g_min[CD_SLOTS]; // encoded mins; zero-init; self-reset
__device__ float g_part[CD_SB];
__device__ unsigned int g_fcnt;

typedef unsigned long long u64;

__device__ __forceinline__ u64 pack2(float v) {
    u64 r;
    unsigned int u = __float_as_uint(v);
    asm("mov.b64 %0, {%1, %1};" : "=l"(r) : "r"(u));
    return r;
}

__device__ __forceinline__ u64 fma2(u64 a, u64 b, u64 c) {
    u64 d;
    asm("fma.rn.f32x2 %0, %1, %2, %3;" : "=l"(d) : "l"(a), "l"(b), "l"(c));
    return d;
}

__device__ __forceinline__ u64 add2(u64 a, u64 b) {
    u64 d;
    asm("add.rn.f32x2 %0, %1, %2;" : "=l"(d) : "l"(a), "l"(b));
    return d;
}

__device__ __forceinline__ void unpack2(u64 v, float& lo, float& hi) {
    unsigned int l, h;
    asm("mov.b64 {%0, %1}, %2;" : "=r"(l), "=r"(h) : "l"(v));
    lo = __uint_as_float(l);
    hi = __uint_as_float(h);
}

// Warp-wide max of a u32 in one instruction (sm_80+ REDUX unit).
__device__ __forceinline__ unsigned int redux_max(unsigned int v) {
    unsigned int d;
    asm("redux.sync.max.u32 %0, %1, 0xffffffff;" : "=r"(d) : "r"(v));
    return d;
}

__global__ __launch_bounds__(CD_TPB, 4)
void cd_pair_kernel(const float* __restrict__ p1,
                    const float* __restrict__ p2) {
    __shared__ float4 sy[CD_TPTS];       // pair-interleaved target tile (2KB)

    const int tid  = threadIdx.x;
    const int ts   = blockIdx.x % CD_TSPLIT;
    const int qblk = blockIdx.x / CD_TSPLIT;
    const int b    = blockIdx.y;

    // Q=8 query points from p1; fold -2 into packed coords; xd packed too.
    u64 xq0[CD_Q], xq1[CD_Q], xq2[CD_Q], xd2[CD_Q];
    float mlo[CD_Q], mhi[CD_Q];
    #pragma unroll
    for (int q = 0; q < CD_Q; q++) {
        const int i = qblk * CD_QBLK + q * CD_TPB + tid;
        const float* xp = p1 + ((size_t)b * CD_N + i) * 3;
        const float x0 = xp[0], x1 = xp[1], x2 = xp[2];
        xd2[q] = pack2(x0 * x0 + x1 * x1 + x2 * x2);
        xq0[q] = pack2(-2.0f * x0);
        xq1[q] = pack2(-2.0f * x1);
        xq2[q] = pack2(-2.0f * x2);
        mlo[q] = 3.402823466e38f;
        mhi[q] = 3.402823466e38f;
    }

    // Target tile from p2 (one pair per thread, first 64 threads).
    if (tid < CD_TPAIRS) {
        const float* yp = p2 + ((size_t)b * CD_N + ts * CD_TPTS + 2 * tid) * 3;
        float e0 = yp[0], e1 = yp[1], e2 = yp[2];
        float o0 = yp[3], o1 = yp[4], o2 = yp[5];
        sy[2 * tid]     = make_float4(e0, o0, e1, o1);
        sy[2 * tid + 1] = make_float4(e2, o2,
                                      e0 * e0 + e1 * e1 + e2 * e2,
                                      o0 * o0 + o1 * o1 + o2 * o2);
    }
    __syncthreads();

    const ulonglong2* __restrict__ syu = reinterpret_cast<const ulonglong2*>(sy);
    const int lane = tid & 31;
    const int colbase = CD_COL_BASE + b * CD_N + ts * CD_TPTS;

    #pragma unroll 2
    for (int p = 0; p < CD_TPAIRS; p++) {
        ulonglong2 A  = syu[2 * p];      // y0 pair, y1 pair
        ulonglong2 Bv = syu[2 * p + 1];  // y2 pair, yd pair
        float ce = 3.402823466e38f, co = 3.402823466e38f;
        #pragma unroll
        for (int q = 0; q < CD_Q; q++) {
            u64 d = fma2(xq2[q], Bv.x, Bv.y);
            d = fma2(xq1[q], A.y, d);
            d = fma2(xq0[q], A.x, d);
            u64 e = add2(d, xd2[q]);     // full dist^2 (lo=target e, hi=target o)
            float elo, ehi;
            unpack2(e, elo, ehi);
            mlo[q] = fminf(mlo[q], elo); // row mins (query-private)
            mhi[q] = fminf(mhi[q], ehi);
            ce = fminf(ce, elo);         // col candidates for this target pair
            co = fminf(co, ehi);
        }
        // Warp col-min in ONE instruction on the encoded key, then lane0 atomic.
        unsigned int ke = redux_max(~__float_as_uint(fmaxf(ce, 0.0f)));
        unsigned int ko = redux_max(~__float_as_uint(fmaxf(co, 0.0f)));
        if (lane == 0) {
            atomicMax(&g_min[colbase + 2 * p], ke);
            atomicMax(&g_min[colbase + 2 * p + 1], ko);
        }
    }

    // Row mins: one encoded atomicMax per query.
    #pragma unroll
    for (int q = 0; q < CD_Q; q++) {
        const int i = qblk * CD_QBLK + q * CD_TPB + tid;
        float v = fmaxf(fminf(mlo[q], mhi[q]), 0.0f);
        atomicMax(&g_min[b * CD_N + i], ~__float_as_uint(v));
    }
}

__global__ __launch_bounds__(CD_STPB)
void cd_sum_kernel(float* __restrict__ out) {
    __shared__ float red[CD_STPB];
    __shared__ int s_flag;

    const int tid = threadIdx.x;
    const uint4* gm4 = reinterpret_cast<const uint4*>(g_min);
    const int i4 = blockIdx.x * CD_STPB + tid;        // 16384 uint4 total / 64 blocks

    uint4 k = gm4[i4];
    float acc = __uint_as_float(~k.x) + __uint_as_float(~k.y)
              + __uint_as_float(~k.z) + __uint_as_float(~k.w);
    reinterpret_cast<uint4*>(g_min)[i4] = make_uint4(0u, 0u, 0u, 0u); // reset

    red[tid] = acc;
    __syncthreads();
    #pragma unroll
    for (int s = CD_STPB / 2; s > 0; s >>= 1) {
        if (tid < s) red[tid] += red[tid + s];
        __syncthreads();
    }

    if (tid == 0) {
        g_part[blockIdx.x] = red[0];
        __threadfence();
        unsigned int t = atomicAdd(&g_fcnt, 1u);
        s_flag = (t == CD_SB - 1);
    }
    __syncthreads();

    if (s_flag) {
        float v = (tid < CD_SB) ? g_part[tid] : 0.0f;
        red[tid] = v;
        __syncthreads();
        #pragma unroll
        for (int s = CD_STPB / 2; s > 0; s >>= 1) {
            if (tid < s) red[tid] += red[tid + s];
            __syncthreads();
        }
        if (tid == 0) {
            out[0] = red[0] * (1.0f / ((float)CD_B * (float)CD_N));
            g_fcnt = 0;                              // reset for graph replay
        }
    }
}

extern "C" void kernel_launch(void* const* d_in, const int* in_sizes, int n_in,
                              void* d_out, int out_size) {
    (void)in_sizes; (void)n_in; (void)out_size;
    const float* p1 = (const float*)d_in[0];
    const float* p2 = (const float*)d_in[1];
    float* out = (float*)d_out;

    dim3 grid(CD_NQB * CD_TSPLIT, CD_B);   // 128 x 8 = 1024 blocks
    cd_pair_kernel<<<grid, CD_TPB>>>(p1, p2);
    cd_sum_kernel<<<CD_SB, CD_STPB>>>(out);
}